// round 5
// baseline (speedup 1.0000x reference)
#include <cuda_runtime.h>

#define HWD   96
#define NVOX  (96*96*96)
#define NVOL  8
#define NTOT  (NVOX*NVOL)
#define NELEM (4*NVOX)
#define NWORDS (NTOT/32)        /* 221184 fg-bit words        */

#define TW 8
#define TH 8
#define TROWS (TW*TH)           /* 64 rows per tile           */
#define TVOX (HWD*TW*TH)        /* 6144                       */
#define TILES_W (HWD/TW)        /* 12 */
#define TILES_PER_VOL (TILES_W*TILES_W)   /* 144 */
#define NBLK_LOCAL (NVOL*TILES_PER_VOL)   /* 1152 */
#define NPLANES (TILES_W-1)     /* 11 */

// scratch (device globals: allocation-free per harness rules)
__device__ int           g_label[NTOT];
__device__ unsigned int  g_bits[NWORDS];
__device__ double        g_focal;
__device__ int           g_counts[NVOL];

// ---------------------------------------------------------------------------
__global__ void k_zero()
{
    if (threadIdx.x == 0) g_focal = 0.0;
    if (threadIdx.x < NVOL) g_counts[threadIdx.x] = 0;
}

// ---------------------------------------------------------------------------
// focal reduction + fg bitmask emission (nibble butterfly across 8 lanes)
// ---------------------------------------------------------------------------
__global__ void k_init_focal(const float4* __restrict__ pred,
                             const float4* __restrict__ tgt)
{
    int i4 = blockIdx.x * blockDim.x + threadIdx.x;     // NELEM/4 threads
    float4 x4 = pred[i4];
    float4 t4 = tgt[i4];
    const float* xs = &x4.x;
    const float* ts = &t4.x;
    unsigned int nibp = 0, nibt = 0;
    float fsum = 0.0f;
    #pragma unroll
    for (int k = 0; k < 4; ++k) {
        float x = xs[k], t = ts[k];
        bool bt = t > 0.5f;
        nibp |= (x > 0.0f ? 1u : 0u) << k;
        nibt |= (bt       ? 1u : 0u) << k;
        float e   = __expf(-fabsf(x));
        float inv = 1.0f / (1.0f + e);
        float sp  = fmaxf(x, 0.0f) + __logf(1.0f + e);
        float bce = sp - x * t;
        float p   = (x >= 0.0f) ? inv : e * inv;        // sigmoid(x)
        float pt  = bt ? p : 1.0f - p;
        float at  = bt ? 0.25f : 0.75f;
        float om  = 1.0f - pt;
        fsum += at * om * om * bce;
    }
    int lane = threadIdx.x & 31;
    unsigned int vp = nibp << (4*(lane & 7));
    unsigned int vt = nibt << (4*(lane & 7));
    #pragma unroll
    for (int off = 1; off <= 4; off <<= 1) {
        vp |= __shfl_xor_sync(0xffffffffu, vp, off);
        vt |= __shfl_xor_sync(0xffffffffu, vt, off);
    }
    if ((lane & 7) == 0) {
        g_bits[i4 >> 3]                = vp;
        g_bits[(i4 >> 3) + NELEM/32]   = vt;
    }

    // block reduce focal -> one atomicAdd per block
    double acc = (double)fsum;
    #pragma unroll
    for (int off = 16; off > 0; off >>= 1)
        acc += __shfl_down_sync(0xffffffffu, acc, off);
    __shared__ double s[8];
    int w = threadIdx.x >> 5;
    if (lane == 0) s[w] = acc;
    __syncthreads();
    if (w == 0) {
        acc = (lane < (blockDim.x >> 5)) ? s[lane] : 0.0;
        #pragma unroll
        for (int off = 4; off > 0; off >>= 1)
            acc += __shfl_down_sync(0xffffffffu, acc, off);
        if (lane == 0) atomicAdd(&g_focal, acc);
    }
}

// ---------------------------------------------------------------------------
// shared-memory union-find (labels monotone non-increasing)
// ---------------------------------------------------------------------------
__device__ __forceinline__ int rep_s(int* lab, int v)
{
    int curr = lab[v];
    if (curr != v) {
        int next;
        while (curr > (next = lab[curr])) {
            lab[v] = next;
            v = curr;
            curr = next;
        }
    }
    return curr;
}

__device__ __forceinline__ void unite_s(int* lab, int a, int b)
{
    int ra = rep_s(lab, a);
    int rb = rep_s(lab, b);
    while (ra != rb) {
        if (ra > rb) { int t = ra; ra = rb; rb = t; }
        int old = atomicMin(&lab[rb], ra);
        if (old == rb) return;
        rb = rep_s(lab, old);
    }
}

// ---------------------------------------------------------------------------
// per-tile local CCL (bit-native): every fg voxel emits its tile-root global
// index -> depth-1 global trees
// ---------------------------------------------------------------------------
__global__ __launch_bounds__(256)
void k_local()
{
    __shared__ unsigned int fgb[TROWS*3];
    __shared__ int          lab[TVOX];
    __shared__ int          growbase[TROWS];

    int b   = blockIdx.x;
    int vol = b / TILES_PER_VOL;
    int t   = b % TILES_PER_VOL;
    int w0  = (t % TILES_W) * TW;
    int h0  = (t / TILES_W) * TH;
    int tid = threadIdx.x;
    int gbase = vol * NVOX;

    if (tid < TROWS)
        growbase[tid] = gbase + (h0 + tid/TW)*HWD*HWD + (w0 + tid%TW)*HWD;
    if (tid < TROWS*3) {
        int row = tid / 3, j = tid % 3;
        int gb  = gbase + (h0 + row/TW)*HWD*HWD + (w0 + row%TW)*HWD;
        fgb[tid] = g_bits[(gb >> 5) + j];
    }
    __syncthreads();

    // init labels: run interiors point directly at run starts (depth 1)
    if (tid < TROWS) {
        int base = tid * HWD;
        int rs = 0;
        bool pf = false;
        #pragma unroll
        for (int j = 0; j < 3; ++j) {
            unsigned int m = fgb[tid*3 + j];
            for (int k = 0; k < 32; ++k) {
                int l = base + 32*j + k;
                bool f = (m >> k) & 1u;
                if (f && !pf) rs = l;
                lab[l] = f ? rs : l;
                pf = f;
            }
        }
    }
    __syncthreads();

    // unions: 112 row pairs (+W: 56, +H: 56) x 3 words
    for (int item = tid; item < 112*3; item += 256) {
        int pair = item / 3, j = item % 3;
        int rA, rB;
        if (pair < 56) {                        // +W
            int h = pair / 7, w = pair % 7;
            rA = h*TW + w;  rB = rA + 1;
        } else {                                // +H
            int i = pair - 56;
            rA = i;         rB = i + TW;
        }
        unsigned int mA = fgb[rA*3 + j];
        unsigned int mB = fgb[rB*3 + j];
        unsigned int ov = mA & mB;
        if (!ov) continue;
        unsigned int carry = (j > 0) ?
            ((fgb[rA*3 + j-1] >> 31) & (fgb[rB*3 + j-1] >> 31) & 1u) : 0u;
        unsigned int us = ov & ~((ov << 1) | carry);
        int baseA = rA*HWD + 32*j, baseB = rB*HWD + 32*j;
        while (us) {
            int bit = __ffs(us) - 1;
            us &= us - 1;
            unite_s(lab, baseA + bit, baseB + bit);
        }
    }
    __syncthreads();

    // emit: every voxel writes final root's GLOBAL index (bg writes self)
    for (int item = tid; item < TROWS*3; item += 256) {
        int row = item / 3, j = item % 3;
        unsigned int m = fgb[item];
        int lbase = row*HWD + 32*j;
        int gb    = growbase[row];
        int last_key = -1, last_r = 0;
        int outv[4];
        #pragma unroll
        for (int q = 0; q < 8; ++q) {
            #pragma unroll
            for (int k = 0; k < 4; ++k) {
                int bit = 4*q + k;
                int l   = lbase + bit;
                int r;
                if ((m >> bit) & 1u) {
                    int key = lab[l];
                    if (key == last_key) r = last_r;
                    else {
                        r = key;
                        int n;
                        while ((n = lab[r]) != r) r = n;
                        last_key = key; last_r = r;
                    }
                } else r = l;
                outv[k] = growbase[r / HWD] + (r % HWD);
            }
            ((int4*)(g_label + gb + 32*j))[q] =
                make_int4(outv[0], outv[1], outv[2], outv[3]);
        }
    }
}

// ---------------------------------------------------------------------------
// global union-find over depth-1 trees (boundary links, 16-bit chunks)
// ---------------------------------------------------------------------------
__device__ __forceinline__ int rep_g(int v)
{
    int curr = g_label[v];
    if (curr != v) {
        int next;
        while (curr > (next = g_label[curr])) {
            g_label[v] = next;
            v = curr;
            curr = next;
        }
    }
    return curr;
}

__device__ __forceinline__ void unite_g(int a, int b)
{
    int ra = rep_g(a);
    int rb = rep_g(b);
    while (ra != rb) {
        if (ra > rb) { int t = ra; ra = rb; rb = t; }
        int old = atomicMin(&g_label[rb], ra);
        if (old == rb) return;
        rb = rep_g(old);
    }
}

#define ROWS_PER_AXIS (NVOL * NPLANES * HWD)   /* 8448 row pairs per axis */
#define BITEMS (2 * ROWS_PER_AXIS * 6)         /* 101376 16-bit work items */

__global__ void k_boundary()
{
    int tid = blockIdx.x * blockDim.x + threadIdx.x;
    if (tid >= BITEMS) return;
    int part = tid % 6;
    int rp   = tid / 6;
    int j    = part >> 1;              // word 0..2
    int c    = part & 1;               // 16-bit half
    int axis = rp / ROWS_PER_AXIS;
    int u    = rp % ROWS_PER_AXIS;
    int vol  = u / (NPLANES * HWD);
    int r2   = u % (NPLANES * HWD);
    int p    = r2 / HWD;
    int q    = r2 % HWD;
    int offA, offB;
    if (axis == 0) {                   // w = 8p+7 -> w+1
        offA = vol*NVOX + q*HWD*HWD + (TW*p + TW-1)*HWD;
        offB = offA + HWD;
    } else {                           // h = 8p+7 -> h+1
        offA = vol*NVOX + (TH*p + TH-1)*HWD*HWD + q*HWD;
        offB = offA + HWD*HWD;
    }
    int wA = (offA >> 5) + j;
    int wB = (offB >> 5) + j;
    unsigned int mA = g_bits[wA];
    unsigned int mB = g_bits[wB];
    unsigned int ov = mA & mB;
    if (!ov) return;
    unsigned int carry = (j > 0) ?
        ((g_bits[wA-1] >> 31) & (g_bits[wB-1] >> 31) & 1u) : 0u;
    unsigned int us = ov & ~((ov << 1) | carry);
    us &= c ? 0xFFFF0000u : 0x0000FFFFu;
    int dbase = 32*j;
    while (us) {
        int bit = __ffs(us) - 1;
        us &= us - 1;
        unite_g(offA + dbase + bit, offB + dbase + bit);
    }
}

// ---------------------------------------------------------------------------
// count run-start roots per volume (32 voxels/thread, bitmask-native)
// ---------------------------------------------------------------------------
__global__ void k_count()
{
    int w = blockIdx.x * 256 + threadIdx.x;     // NWORDS threads
    unsigned int m = g_bits[w];
    int c = 0;
    if (m) {
        unsigned int carry = (w % 3 == 0) ? 0u : (g_bits[w-1] >> 31);
        unsigned int starts = m & ~((m << 1) | (carry & 1u));
        int base = w * 32;
        while (starts) {
            int bit = __ffs(starts) - 1;
            starts &= starts - 1;
            int idx = base + bit;
            if (g_label[idx] == idx) ++c;
        }
    }
    #pragma unroll
    for (int off = 16; off > 0; off >>= 1)
        c += __shfl_down_sync(0xffffffffu, c, off);
    __shared__ int s;
    if (threadIdx.x == 0) s = 0;
    __syncthreads();
    if ((threadIdx.x & 31) == 0 && c) atomicAdd(&s, c);
    __syncthreads();
    if (threadIdx.x == 0 && s > 0)
        atomicAdd(&g_counts[blockIdx.x / (NVOX/32/256)], s);
}

// ---------------------------------------------------------------------------
__global__ void k_final(float* __restrict__ out)
{
    float c0 = (float)g_counts[0], c1 = (float)g_counts[1];
    float c2 = (float)g_counts[2], c3 = (float)g_counts[3];
    float t0 = (float)g_counts[4], t1 = (float)g_counts[5];
    float t2 = (float)g_counts[6], t3 = (float)g_counts[7];
    float ccp0 = 0.5f*(c0 + c2), ccp1 = 0.5f*(c1 + c3);
    float cct0 = 0.5f*(t0 + t2), cct1 = 0.5f*(t1 + t3);
    float topo = 0.5f*(fabsf(ccp0 - cct0) + fabsf(ccp1 - cct1));
    float focal = (float)(g_focal / (double)NELEM);
    out[0] = focal + 0.1f * topo;
}

// ---------------------------------------------------------------------------
extern "C" void kernel_launch(void* const* d_in, const int* in_sizes, int n_in,
                              void* d_out, int out_size)
{
    const float4* pred = (const float4*)d_in[0];
    const float4* tgt  = (const float4*)d_in[1];
    float*        out  = (float*)d_out;

    const int T = 256;
    k_zero      <<<1, 32>>>();
    k_init_focal<<<NELEM/4/T, T>>>(pred, tgt);
    k_local     <<<NBLK_LOCAL, T>>>();
    k_boundary  <<<(BITEMS + T-1)/T, T>>>();
    k_count     <<<NWORDS/T, T>>>();
    k_final     <<<1, 1>>>(out);
}

// round 6
// speedup vs baseline: 1.8654x; 1.8654x over previous
#include <cuda_runtime.h>

#define HWD   96
#define NVOX  (96*96*96)
#define NVOL  8
#define NTOT  (NVOX*NVOL)
#define NELEM (4*NVOX)
#define NWORDS (NTOT/32)        /* 221184 fg-bit words        */

#define TW 8
#define TH 8
#define TROWS (TW*TH)           /* 64 rows per tile           */
#define TVOX (HWD*TW*TH)        /* 6144                       */
#define TILES_W (HWD/TW)        /* 12 */
#define TILES_PER_VOL (TILES_W*TILES_W)   /* 144 */
#define NBLK_LOCAL (NVOL*TILES_PER_VOL)   /* 1152 */
#define NPLANES (TILES_W-1)     /* 11 */

// scratch (device globals: allocation-free per harness rules)
__device__ int           g_label[NTOT];
__device__ unsigned int  g_bits[NWORDS];
__device__ double        g_focal;
__device__ int           g_counts[NVOL];

// ---------------------------------------------------------------------------
// run start within a 96-bit row mask m[3], for voxel at bit position d.
// Returns largest s <= d with bit (s-1) clear (or 0). Pure ALU, no mem chain.
// ---------------------------------------------------------------------------
__device__ __forceinline__ int run_start3(const unsigned int* m, int d)
{
    int j = d >> 5, k = d & 31;
    unsigned int below = (k == 0) ? 0u : ((1u << k) - 1u);
    unsigned int x = ~m[j] & below;            // zeros strictly below d in word j
    if (x) return (j << 5) + (32 - __clz(x));
    while (--j >= 0) {
        x = ~m[j];
        if (x) return (j << 5) + (32 - __clz(x));
    }
    return 0;
}

// ---------------------------------------------------------------------------
__global__ void k_zero()
{
    if (threadIdx.x == 0) g_focal = 0.0;
    if (threadIdx.x < NVOL) g_counts[threadIdx.x] = 0;
}

// ---------------------------------------------------------------------------
// focal reduction + fg bitmask emission (nibble butterfly across 8 lanes)
// ---------------------------------------------------------------------------
__global__ void k_init_focal(const float4* __restrict__ pred,
                             const float4* __restrict__ tgt)
{
    int i4 = blockIdx.x * blockDim.x + threadIdx.x;     // NELEM/4 threads
    float4 x4 = pred[i4];
    float4 t4 = tgt[i4];
    const float* xs = &x4.x;
    const float* ts = &t4.x;
    unsigned int nibp = 0, nibt = 0;
    float fsum = 0.0f;
    #pragma unroll
    for (int k = 0; k < 4; ++k) {
        float x = xs[k], t = ts[k];
        bool bt = t > 0.5f;
        nibp |= (x > 0.0f ? 1u : 0u) << k;
        nibt |= (bt       ? 1u : 0u) << k;
        float e   = __expf(-fabsf(x));
        float inv = 1.0f / (1.0f + e);
        float sp  = fmaxf(x, 0.0f) + __logf(1.0f + e);
        float bce = sp - x * t;
        float p   = (x >= 0.0f) ? inv : e * inv;        // sigmoid(x)
        float pt  = bt ? p : 1.0f - p;
        float at  = bt ? 0.25f : 0.75f;
        float om  = 1.0f - pt;
        fsum += at * om * om * bce;
    }
    int lane = threadIdx.x & 31;
    unsigned int vp = nibp << (4*(lane & 7));
    unsigned int vt = nibt << (4*(lane & 7));
    #pragma unroll
    for (int off = 1; off <= 4; off <<= 1) {
        vp |= __shfl_xor_sync(0xffffffffu, vp, off);
        vt |= __shfl_xor_sync(0xffffffffu, vt, off);
    }
    if ((lane & 7) == 0) {
        g_bits[i4 >> 3]                = vp;
        g_bits[(i4 >> 3) + NELEM/32]   = vt;
    }

    double acc = (double)fsum;
    #pragma unroll
    for (int off = 16; off > 0; off >>= 1)
        acc += __shfl_down_sync(0xffffffffu, acc, off);
    __shared__ double s[8];
    int w = threadIdx.x >> 5;
    if (lane == 0) s[w] = acc;
    __syncthreads();
    if (w == 0) {
        acc = (lane < (blockDim.x >> 5)) ? s[lane] : 0.0;
        #pragma unroll
        for (int off = 4; off > 0; off >>= 1)
            acc += __shfl_down_sync(0xffffffffu, acc, off);
        if (lane == 0) atomicAdd(&g_focal, acc);
    }
}

// ---------------------------------------------------------------------------
// shared-memory union-find (labels monotone non-increasing)
// ---------------------------------------------------------------------------
__device__ __forceinline__ int rep_s(int* lab, int v)
{
    int curr = lab[v];
    if (curr != v) {
        int next;
        while (curr > (next = lab[curr])) {
            lab[v] = next;
            v = curr;
            curr = next;
        }
    }
    return curr;
}

__device__ __forceinline__ void unite_s(int* lab, int a, int b)
{
    int ra = rep_s(lab, a);
    int rb = rep_s(lab, b);
    while (ra != rb) {
        if (ra > rb) { int t = ra; ra = rb; rb = t; }
        int old = atomicMin(&lab[rb], ra);
        if (old == rb) return;
        rb = rep_s(lab, old);
    }
}

// ---------------------------------------------------------------------------
// per-tile local CCL over run starts; emit run-start labels only
// ---------------------------------------------------------------------------
__global__ __launch_bounds__(256)
void k_local()
{
    __shared__ unsigned int fgb[TROWS*3];
    __shared__ int          lab[TVOX];
    __shared__ int          growbase[TROWS];

    int b   = blockIdx.x;
    int vol = b / TILES_PER_VOL;
    int t   = b % TILES_PER_VOL;
    int w0  = (t % TILES_W) * TW;
    int h0  = (t / TILES_W) * TH;
    int tid = threadIdx.x;
    int gbase = vol * NVOX;

    if (tid < TROWS)
        growbase[tid] = gbase + (h0 + tid/TW)*HWD*HWD + (w0 + tid%TW)*HWD;
    if (tid < TROWS*3) {
        int row = tid / 3, j = tid % 3;
        int gb  = gbase + (h0 + row/TW)*HWD*HWD + (w0 + row%TW)*HWD;
        fgb[tid] = g_bits[(gb >> 5) + j];
    }
    // labels = self (only run-start slots are ever used)
    for (int item = tid; item < TVOX/4; item += 256) {
        int base = item*4;
        ((int4*)lab)[item] = make_int4(base, base+1, base+2, base+3);
    }
    __syncthreads();

    // unions: 112 row pairs (+W: 56, +H: 56) x 3 words, run-start operands
    for (int item = tid; item < 112*3; item += 256) {
        int pair = item / 3, j = item % 3;
        int rA, rB;
        if (pair < 56) {                        // +W
            int h = pair / 7, w = pair % 7;
            rA = h*TW + w;  rB = rA + 1;
        } else {                                // +H
            int i = pair - 56;
            rA = i;         rB = i + TW;
        }
        unsigned int mA = fgb[rA*3 + j];
        unsigned int mB = fgb[rB*3 + j];
        unsigned int ov = mA & mB;
        if (!ov) continue;
        unsigned int carry = (j > 0) ?
            ((fgb[rA*3 + j-1] & fgb[rB*3 + j-1]) >> 31) : 0u;
        unsigned int us = ov & ~((ov << 1) | carry);
        while (us) {
            int bit = __ffs(us) - 1;
            us &= us - 1;
            int d  = 32*j + bit;
            int sA = rA*HWD + run_start3(&fgb[rA*3], d);
            int sB = rB*HWD + run_start3(&fgb[rB*3], d);
            unite_s(lab, sA, sB);
        }
    }
    __syncthreads();

    // emit: per run start, write global label = global(root)
    for (int item = tid; item < TROWS*3; item += 256) {
        int row = item / 3, j = item % 3;
        unsigned int m = fgb[item];
        if (!m) continue;
        unsigned int carry = (j > 0) ? (fgb[item-1] >> 31) : 0u;
        unsigned int st = m & ~((m << 1) | (carry & 1u));
        int gb = growbase[row];
        while (st) {
            int bit = __ffs(st) - 1;
            st &= st - 1;
            int s = row*HWD + 32*j + bit;
            int r = lab[s];
            while (r != lab[r]) r = lab[r];
            g_label[gb + 32*j + bit] = growbase[r / HWD] + (r % HWD);
        }
    }
}

// ---------------------------------------------------------------------------
// global union-find over run-start labels (boundary links, 8-bit chunks)
// ---------------------------------------------------------------------------
__device__ __forceinline__ int rep_g(int v)
{
    int curr = g_label[v];
    if (curr != v) {
        int next;
        while (curr > (next = g_label[curr])) {
            g_label[v] = next;
            v = curr;
            curr = next;
        }
    }
    return curr;
}

__device__ __forceinline__ void unite_g(int a, int b)
{
    int ra = rep_g(a);
    int rb = rep_g(b);
    while (ra != rb) {
        if (ra > rb) { int t = ra; ra = rb; rb = t; }
        int old = atomicMin(&g_label[rb], ra);
        if (old == rb) return;
        rb = rep_g(old);
    }
}

#define ROWS_PER_AXIS (NVOL * NPLANES * HWD)   /* 8448 row pairs per axis */
#define BITEMS (2 * ROWS_PER_AXIS * 12)        /* 202752 8-bit work items */

__global__ void k_boundary()
{
    int tid = blockIdx.x * blockDim.x + threadIdx.x;
    if (tid >= BITEMS) return;
    int part = tid % 12;               // byte chunk 0..11
    int rp   = tid / 12;
    int j    = part >> 2;              // word 0..2
    int c    = part & 3;               // byte within word
    int axis = rp / ROWS_PER_AXIS;
    int u    = rp % ROWS_PER_AXIS;
    int vol  = u / (NPLANES * HWD);
    int r2   = u % (NPLANES * HWD);
    int p    = r2 / HWD;
    int q    = r2 % HWD;
    int offA, offB;
    if (axis == 0) {                   // w = 8p+7 -> w+1
        offA = vol*NVOX + q*HWD*HWD + (TW*p + TW-1)*HWD;
        offB = offA + HWD;
    } else {                           // h = 8p+7 -> h+1
        offA = vol*NVOX + (TH*p + TH-1)*HWD*HWD + q*HWD;
        offB = offA + HWD*HWD;
    }
    unsigned int wA[3], wB[3];
    #pragma unroll
    for (int k = 0; k < 3; ++k) {
        wA[k] = g_bits[(offA >> 5) + k];
        wB[k] = g_bits[(offB >> 5) + k];
    }
    unsigned int ov = wA[j] & wB[j];
    if (!ov) return;
    unsigned int carry = (j > 0) ? ((wA[j-1] & wB[j-1]) >> 31) : 0u;
    unsigned int us = ov & ~((ov << 1) | carry);
    us &= 0xFFu << (8*c);              // this thread's byte chunk
    while (us) {
        int bit = __ffs(us) - 1;
        us &= us - 1;
        int d = 32*j + bit;
        unite_g(offA + run_start3(wA, d), offB + run_start3(wB, d));
    }
}

// ---------------------------------------------------------------------------
// count run-start roots per volume (32 voxels/thread, bitmask-native)
// ---------------------------------------------------------------------------
__global__ void k_count()
{
    int w = blockIdx.x * 256 + threadIdx.x;     // NWORDS threads
    unsigned int m = g_bits[w];
    int c = 0;
    if (m) {
        unsigned int carry = (w % 3 == 0) ? 0u : (g_bits[w-1] >> 31);
        unsigned int starts = m & ~((m << 1) | (carry & 1u));
        int base = w * 32;
        while (starts) {
            int bit = __ffs(starts) - 1;
            starts &= starts - 1;
            int idx = base + bit;
            if (g_label[idx] == idx) ++c;
        }
    }
    #pragma unroll
    for (int off = 16; off > 0; off >>= 1)
        c += __shfl_down_sync(0xffffffffu, c, off);
    __shared__ int s;
    if (threadIdx.x == 0) s = 0;
    __syncthreads();
    if ((threadIdx.x & 31) == 0 && c) atomicAdd(&s, c);
    __syncthreads();
    if (threadIdx.x == 0 && s > 0)
        atomicAdd(&g_counts[blockIdx.x / (NVOX/32/256)], s);
}

// ---------------------------------------------------------------------------
__global__ void k_final(float* __restrict__ out)
{
    float c0 = (float)g_counts[0], c1 = (float)g_counts[1];
    float c2 = (float)g_counts[2], c3 = (float)g_counts[3];
    float t0 = (float)g_counts[4], t1 = (float)g_counts[5];
    float t2 = (float)g_counts[6], t3 = (float)g_counts[7];
    float ccp0 = 0.5f*(c0 + c2), ccp1 = 0.5f*(c1 + c3);
    float cct0 = 0.5f*(t0 + t2), cct1 = 0.5f*(t1 + t3);
    float topo = 0.5f*(fabsf(ccp0 - cct0) + fabsf(ccp1 - cct1));
    float focal = (float)(g_focal / (double)NELEM);
    out[0] = focal + 0.1f * topo;
}

// ---------------------------------------------------------------------------
extern "C" void kernel_launch(void* const* d_in, const int* in_sizes, int n_in,
                              void* d_out, int out_size)
{
    const float4* pred = (const float4*)d_in[0];
    const float4* tgt  = (const float4*)d_in[1];
    float*        out  = (float*)d_out;

    const int T = 256;
    k_zero      <<<1, 32>>>();
    k_init_focal<<<NELEM/4/T, T>>>(pred, tgt);
    k_local     <<<NBLK_LOCAL, T>>>();
    k_boundary  <<<(BITEMS + T-1)/T, T>>>();
    k_count     <<<NWORDS/T, T>>>();
    k_final     <<<1, 1>>>(out);
}